// round 7
// baseline (speedup 1.0000x reference)
#include <cuda_runtime.h>
#include <math.h>

#define B_DIM 128
#define S_DIM 512
#define IN_DIM 128
#define D_DIM 64
#define G_DIM 256   // 4*D
#define TILE_R 64

typedef unsigned long long ull;

// ---- packed f32x2 helpers (Blackwell; ptxas never auto-fuses these) ----
__device__ __forceinline__ void ffma2(ull& a, ull x, ull y) {
    asm("fma.rn.f32x2 %0, %1, %2, %0;" : "+l"(a) : "l"(x), "l"(y));
}
__device__ __forceinline__ ull fmaf2(ull a, ull b, ull c) {
    ull d; asm("fma.rn.f32x2 %0, %1, %2, %3;" : "=l"(d) : "l"(a), "l"(b), "l"(c)); return d;
}
__device__ __forceinline__ ull mulf2(ull x, ull y) {
    ull r; asm("mul.rn.f32x2 %0, %1, %2;" : "=l"(r) : "l"(x), "l"(y)); return r;
}
__device__ __forceinline__ ull addf2(ull x, ull y) {
    ull r; asm("add.rn.f32x2 %0, %1, %2;" : "=l"(r) : "l"(x), "l"(y)); return r;
}
__device__ __forceinline__ ull packf2(float lo, float hi) {
    ull r; asm("mov.b64 %0, {%1, %2};" : "=l"(r) : "f"(lo), "f"(hi)); return r;
}
__device__ __forceinline__ float2 unpackf2(ull v) {
    float2 f; asm("mov.b64 {%0, %1}, %2;" : "=f"(f.x), "=f"(f.y) : "l"(v)); return f;
}

// Scratch (sanctioned __device__ globals)
__device__ float g_xs[(size_t)S_DIM * B_DIM * G_DIM];   // [s][b][4D]
__device__ float g_Wc[IN_DIM * G_DIM];                  // W_in @ W_s
__device__ float g_bc[G_DIM];                           // b_in @ W_s + b_s

// ---------------------------------------------------------------------------
// Kernel 1: fold input projection into sLSTM input weights.
// ---------------------------------------------------------------------------
__global__ void combine_weights(const float* __restrict__ W_in,
                                const float* __restrict__ b_in,
                                const float* __restrict__ W_s,
                                const float* __restrict__ b_s) {
    int j = threadIdx.x;
    int d = blockIdx.x;
    if (d < IN_DIM) {
        float acc = 0.f;
#pragma unroll
        for (int e = 0; e < D_DIM; e++)
            acc += W_in[d * D_DIM + e] * W_s[e * G_DIM + j];
        g_Wc[d * G_DIM + j] = acc;
    } else {
        float acc = b_s[j];
#pragma unroll
        for (int e = 0; e < D_DIM; e++)
            acc += b_in[e] * W_s[e * G_DIM + j];
        g_bc[j] = acc;
    }
}

// ---------------------------------------------------------------------------
// Kernel 2: xs[s][b][j] = x[b][s][:] @ W_comb[:,j] + b_comb[j]  (packed f32x2)
// ---------------------------------------------------------------------------
__global__ __launch_bounds__(256) void xs_gemm(const float* __restrict__ x) {
    __shared__ __align__(16) float xsm[TILE_R][IN_DIM];
    int t = threadIdx.x;
    int row0 = blockIdx.x * TILE_R;

    const float4* xg = reinterpret_cast<const float4*>(x + (size_t)row0 * IN_DIM);
    float4* xs4 = reinterpret_cast<float4*>(&xsm[0][0]);
#pragma unroll
    for (int i = 0; i < (TILE_R * IN_DIM / 4) / 256; i++)
        xs4[t + i * 256] = xg[t + i * 256];

    ull w2[64];
#pragma unroll
    for (int i = 0; i < 64; i++)
        w2[i] = packf2(g_Wc[(2 * i) * G_DIM + t], g_Wc[(2 * i + 1) * G_DIM + t]);
    float bc = g_bc[t];
    __syncthreads();

    for (int r = 0; r < TILE_R; r += 4) {
        ull a0 = 0, a1 = 0, a2 = 0, a3 = 0;
        const ulonglong2* p0 = reinterpret_cast<const ulonglong2*>(xsm[r + 0]);
        const ulonglong2* p1 = reinterpret_cast<const ulonglong2*>(xsm[r + 1]);
        const ulonglong2* p2 = reinterpret_cast<const ulonglong2*>(xsm[r + 2]);
        const ulonglong2* p3 = reinterpret_cast<const ulonglong2*>(xsm[r + 3]);
#pragma unroll
        for (int dq = 0; dq < 32; dq++) {
            ulonglong2 v0 = p0[dq]; ffma2(a0, v0.x, w2[2*dq]); ffma2(a0, v0.y, w2[2*dq+1]);
            ulonglong2 v1 = p1[dq]; ffma2(a1, v1.x, w2[2*dq]); ffma2(a1, v1.y, w2[2*dq+1]);
            ulonglong2 v2 = p2[dq]; ffma2(a2, v2.x, w2[2*dq]); ffma2(a2, v2.y, w2[2*dq+1]);
            ulonglong2 v3 = p3[dq]; ffma2(a3, v3.x, w2[2*dq]); ffma2(a3, v3.y, w2[2*dq+1]);
        }
#pragma unroll
        for (int rr = 0; rr < 4; rr++) {
            ull av = (rr == 0) ? a0 : (rr == 1) ? a1 : (rr == 2) ? a2 : a3;
            float2 f = unpackf2(av);
            int row = row0 + r + rr;
            int bb = row >> 9;
            int ss = row & 511;
            g_xs[((size_t)ss * B_DIM + bb) * G_DIM + t] = f.x + f.y + bc;
        }
    }
}

// ---------------------------------------------------------------------------
// Kernel 3: persistent recurrence, 1 CTA/batch, 256 threads, 3 barriers/step.
// xs stream prefetched 4 steps deep (rotating registers) so the DRAM/L2
// latency of the per-step 1KB xs read is fully hidden.
// ---------------------------------------------------------------------------
__global__ __launch_bounds__(256) void recur(
    const float* __restrict__ R_s,
    const float* __restrict__ ln_g, const float* __restrict__ ln_b,
    const float* __restrict__ Wq, const float* __restrict__ Wk,
    const float* __restrict__ Wv,
    const float* __restrict__ wi, const float* __restrict__ bi_p,
    const float* __restrict__ wf, const float* __restrict__ bf_p,
    const float* __restrict__ Wo, const float* __restrict__ bo,
    const float* __restrict__ W_fuse, const float* __restrict__ b_fuse,
    float* __restrict__ out)
{
    __shared__ __align__(16) float hs[64], hso[64], ksm[64], vsm[64], nm[64];
    __shared__ __align__(16) float gact[256];
    __shared__ float scl[2];                          // im, fm
    __shared__ __align__(16) float qsm[64], omsm[64], numsm[64], hmsm[64];
    __shared__ float red2[2];
    __shared__ float gpart[4][64];

    int t = threadIdx.x;
    int b = blockIdx.x;
    int lane = t & 31;

    // recurrent weight column t, packed (pair i covers rows 2i,2i+1 of 64)
    ull R2[32];
#pragma unroll
    for (int i = 0; i < 32; i++)
        R2[i] = packf2(R_s[(2 * i) * G_DIM + t], R_s[(2 * i + 1) * G_DIM + t]);

    ull W2[32];
    if (t < 128) {
        const float* Wsel = (t < 64) ? Wk : Wv;
        int c = t & 63;
#pragma unroll
        for (int i = 0; i < 32; i++)
            W2[i] = packf2(Wsel[(2 * i) * 64 + c], Wsel[(2 * i + 1) * 64 + c]);
    }

    // warp-0 per-lane LN / gate constants (lane handles dims d0=lane, d1=lane+32)
    float cs0 = 0.f, cs1 = 0.f, ns0 = 1.f, ns1 = 1.f;
    float g0 = 0.f, g1 = 0.f, lb0 = 0.f, lb1 = 0.f;
    float gwi0 = 0.f, gwi1 = 0.f, gwf0 = 0.f, gwf1 = 0.f;
    float Sgwi = 0.f, Sgwf = 0.f, Sbwi = 0.f, Sbwf = 0.f;
    if (t < 32) {
        int d0 = t, d1 = t + 32;
        g0 = ln_g[d0]; g1 = ln_g[d1]; lb0 = ln_b[d0]; lb1 = ln_b[d1];
        float wi0 = wi[d0], wi1 = wi[d1], wf0 = wf[d0], wf1 = wf[d1];
        gwi0 = g0 * wi0; gwi1 = g1 * wi1; gwf0 = g0 * wf0; gwf1 = g1 * wf1;
        float sa = gwi0 + gwi1, sb = gwf0 + gwf1;
        float sc = lb0 * wi0 + lb1 * wi1, sd = lb0 * wf0 + lb1 * wf1;
#pragma unroll
        for (int off = 16; off > 0; off >>= 1) {
            sa += __shfl_xor_sync(0xffffffffu, sa, off);
            sb += __shfl_xor_sync(0xffffffffu, sb, off);
            sc += __shfl_xor_sync(0xffffffffu, sc, off);
            sd += __shfl_xor_sync(0xffffffffu, sd, off);
        }
        Sgwi = sa; Sgwf = sb; Sbwi = sc; Sbwf = sd;
    }
    if (t < 64) { hs[t] = 0.f; nm[t] = 0.f; }
    float bi = bi_p[0];
    float bf = bf_p[0];

    ull C2[8];
#pragma unroll
    for (int i = 0; i < 8; i++) C2[i] = 0ull;

    __syncthreads();

    const size_t BG = (size_t)B_DIM * G_DIM;
    const float* xsp = g_xs + (size_t)b * G_DIM + t;
    // 4-deep rotating prefetch of the xs stream
    float gn0 = xsp[0];
    float gn1 = xsp[1 * BG];
    float gn2 = xsp[2 * BG];
    float gn3 = xsp[3 * BG];

    const int ci = t >> 2;           // C_m row owned (4 threads per row)
    const int jb = (t & 3) << 4;     // 16-column slice

    for (int s = 0; s < S_DIM; s++) {
        // ---- Phase A: g = xs_t + h_s @ R_s ; activation ----
        float gv = gn0;
        gn0 = gn1; gn1 = gn2; gn2 = gn3;
        {
            int sn = (s + 4 < S_DIM) ? (s + 4) : (S_DIM - 1);
            gn3 = xsp[(size_t)sn * BG];
        }
        {
            ull a0 = 0, a1 = 0, a2 = 0, a3 = 0;
            const ulonglong2* h2 = reinterpret_cast<const ulonglong2*>(hs);
#pragma unroll
            for (int q = 0; q < 8; q++) {
                ulonglong2 u = h2[2 * q];
                ulonglong2 w = h2[2 * q + 1];
                ffma2(a0, u.x, R2[4 * q]);
                ffma2(a1, u.y, R2[4 * q + 1]);
                ffma2(a2, w.x, R2[4 * q + 2]);
                ffma2(a3, w.y, R2[4 * q + 3]);
            }
            a0 = addf2(a0, a1); a2 = addf2(a2, a3); a0 = addf2(a0, a2);
            float2 p = unpackf2(a0);
            gv += p.x + p.y;
        }
        float act;
        if (t < 64) {                       // tanh
            float e = __expf(2.f * gv);
            act = 1.f - __fdividef(2.f, e + 1.f);
        } else if (t < 128) {               // exp
            act = __expf(gv);
        } else {                            // sigmoid
            float e = __expf(-gv);
            act = __fdividef(1.f, 1.f + e);
        }
        gact[t] = act;
        __syncthreads();                                   // s1

        // ---- Phase B (warp 0): state, LN, im/fm — one fused reduction ----
        if (t < 32) {
            int d0 = t, d1 = t + 32;
            float z0 = gact[d0], i0 = gact[64 + d0], f0 = gact[128 + d0], o0 = gact[192 + d0];
            float z1 = gact[d1], i1 = gact[64 + d1], f1 = gact[128 + d1], o1 = gact[192 + d1];
            cs0 = f0 * cs0 + i0 * z0; ns0 = f0 * ns0 + i0;
            cs1 = f1 * cs1 + i1 * z1; ns1 = f1 * ns1 + i1;
            float h0 = __fdividef(o0 * cs0, ns0);
            float h1 = __fdividef(o1 * cs1, ns1);
            hs[d0] = h0; hs[d1] = h1;
            float r1 = h0 + h1;
            float r2 = h0 * h0 + h1 * h1;
            float r3 = h0 * gwi0 + h1 * gwi1;
            float r4 = h0 * gwf0 + h1 * gwf1;
#pragma unroll
            for (int off = 16; off > 0; off >>= 1) {
                r1 += __shfl_xor_sync(0xffffffffu, r1, off);
                r2 += __shfl_xor_sync(0xffffffffu, r2, off);
                r3 += __shfl_xor_sync(0xffffffffu, r3, off);
                r4 += __shfl_xor_sync(0xffffffffu, r4, off);
            }
            float mu = r1 * 0.015625f;
            float inv = rsqrtf(r2 * 0.015625f - mu * mu + 1e-5f);
            hso[d0] = (h0 - mu) * inv * g0 + lb0;
            hso[d1] = (h1 - mu) * inv * g1 + lb1;
            if (t == 0) {
                float pi = inv * (r3 - mu * Sgwi) + Sbwi + bi;
                float pf = inv * (r4 - mu * Sgwf) + Sbwf + bf;
                scl[0] = __expf(pi);
                float ef = __expf(-pf);
                scl[1] = __fdividef(1.f, 1.f + ef);
            }
        }
        __syncthreads();                                   // s2

        // ---- Phase C: k = hso@Wk * d^-1/2 ; v = hso@Wv (threads 0..127) ----
        if (t < 128) {
            ull a0 = 0, a1 = 0, a2 = 0, a3 = 0;
            const ulonglong2* h2 = reinterpret_cast<const ulonglong2*>(hso);
#pragma unroll
            for (int q = 0; q < 8; q++) {
                ulonglong2 u = h2[2 * q];
                ulonglong2 w = h2[2 * q + 1];
                ffma2(a0, u.x, W2[4 * q]);
                ffma2(a1, u.y, W2[4 * q + 1]);
                ffma2(a2, w.x, W2[4 * q + 2]);
                ffma2(a3, w.y, W2[4 * q + 3]);
            }
            a0 = addf2(a0, a1); a2 = addf2(a2, a3); a0 = addf2(a0, a2);
            float2 p = unpackf2(a0);
            float acc = p.x + p.y;
            if (t < 64) ksm[t] = acc * 0.125f;
            else        vsm[t - 64] = acc;
        }
        __syncthreads();                                   // s3

        // ---- Phase D: C_m rank-1 update, n_m update ----
        {
            float im = scl[0], fm = scl[1];
            float imv = im * vsm[ci];
            ull fm2 = packf2(fm, fm);
            ull iv2 = packf2(imv, imv);
            const ulonglong2* k2 = reinterpret_cast<const ulonglong2*>(ksm + jb);
#pragma unroll
            for (int q = 0; q < 4; q++) {
                ulonglong2 kv = k2[q];
                C2[2 * q]     = fmaf2(C2[2 * q],     fm2, mulf2(kv.x, iv2));
                C2[2 * q + 1] = fmaf2(C2[2 * q + 1], fm2, mulf2(kv.y, iv2));
            }
            if (t < 64) nm[t] = fm * nm[t] + im * ksm[t];
        }
        // no trailing barrier: next-iter hazards all fenced by s1..s3
    }

    // ---- Final-step epilogue: q, om, num, den, h_m, fusion gate ----
    float Creg[16];
#pragma unroll
    for (int i = 0; i < 8; i++) {
        float2 f = unpackf2(C2[i]);
        Creg[2 * i] = f.x; Creg[2 * i + 1] = f.y;
    }
    __syncthreads();
    if (t < 128) {
        int c = t & 63;
        const float* W = (t < 64) ? Wq : Wo;
        float acc = (t < 64) ? 0.f : bo[c];
#pragma unroll
        for (int d = 0; d < 64; d++) acc += hso[d] * W[d * 64 + c];
        if (t < 64) qsm[c] = acc;
        else        omsm[c] = 1.f / (1.f + expf(-acc));
    }
    __syncthreads();
    {
        float np = 0.f;
        const float4* q4p = reinterpret_cast<const float4*>(qsm + jb);
#pragma unroll
        for (int q4 = 0; q4 < 4; q4++) {
            float4 qq = q4p[q4];
            np += Creg[q4*4+0] * qq.x + Creg[q4*4+1] * qq.y
                + Creg[q4*4+2] * qq.z + Creg[q4*4+3] * qq.w;
        }
        np += __shfl_xor_sync(0xffffffffu, np, 1);
        np += __shfl_xor_sync(0xffffffffu, np, 2);
        if ((t & 3) == 0) numsm[ci] = np;
    }
    if (t < 64) {
        float dp = nm[t] * qsm[t];
#pragma unroll
        for (int off = 16; off > 0; off >>= 1)
            dp += __shfl_xor_sync(0xffffffffu, dp, off);
        if (lane == 0) red2[t >> 5] = dp;
    }
    __syncthreads();
    if (t < 64) {
        float den = fmaxf(fabsf(red2[0] + red2[1]), 1.f);
        hmsm[t] = omsm[t] * numsm[t] / den;
    }
    __syncthreads();
    {
        int j = t & 63, rb2 = (t >> 6) * 32;
        float gp = 0.f;
#pragma unroll
        for (int r = 0; r < 32; r++) {
            int rr = rb2 + r;
            float catv = (rr < 64) ? hso[rr] : hmsm[rr - 64];
            gp += catv * W_fuse[rr * 64 + j];
        }
        gpart[t >> 6][j] = gp;
    }
    __syncthreads();
    if (t < 64) {
        float gs = gpart[0][t] + gpart[1][t] + gpart[2][t] + gpart[3][t] + b_fuse[t];
        float gate = 1.f / (1.f + expf(-gs));
        out[b * 64 + t] = gate * hmsm[t] + (1.f - gate) * hso[t];
    }
}

// ---------------------------------------------------------------------------
extern "C" void kernel_launch(void* const* d_in, const int* in_sizes, int n_in,
                              void* d_out, int out_size) {
    const float* x      = (const float*)d_in[0];
    const float* W_in   = (const float*)d_in[1];
    const float* b_in   = (const float*)d_in[2];
    const float* W_s    = (const float*)d_in[3];
    const float* R_s    = (const float*)d_in[4];
    const float* b_s    = (const float*)d_in[5];
    const float* ln_g   = (const float*)d_in[6];
    const float* ln_b   = (const float*)d_in[7];
    const float* Wq     = (const float*)d_in[8];
    const float* Wk     = (const float*)d_in[9];
    const float* Wv     = (const float*)d_in[10];
    const float* wi     = (const float*)d_in[11];
    const float* bi     = (const float*)d_in[12];
    const float* wf     = (const float*)d_in[13];
    const float* bf     = (const float*)d_in[14];
    const float* Wo     = (const float*)d_in[15];
    const float* bo     = (const float*)d_in[16];
    const float* W_fuse = (const float*)d_in[17];
    const float* b_fuse = (const float*)d_in[18];
    float* out = (float*)d_out;

    combine_weights<<<IN_DIM + 1, G_DIM>>>(W_in, b_in, W_s, b_s);
    xs_gemm<<<(B_DIM * S_DIM) / TILE_R, 256>>>(x);
    recur<<<B_DIM, 256>>>(R_s, ln_g, ln_b, Wq, Wk, Wv, wi, bi, wf, bf,
                          Wo, bo, W_fuse, b_fuse, out);
}

// round 8
// speedup vs baseline: 1.2512x; 1.2512x over previous
#include <cuda_runtime.h>
#include <math.h>

#define B_DIM 128
#define S_DIM 512
#define IN_DIM 128
#define D_DIM 64
#define G_DIM 256   // 4*D
#define TILE_R 64

typedef unsigned long long ull;

// ---- packed f32x2 helpers ----
__device__ __forceinline__ void ffma2(ull& a, ull x, ull y) {
    asm("fma.rn.f32x2 %0, %1, %2, %0;" : "+l"(a) : "l"(x), "l"(y));
}
__device__ __forceinline__ ull addf2(ull x, ull y) {
    ull r; asm("add.rn.f32x2 %0, %1, %2;" : "=l"(r) : "l"(x), "l"(y)); return r;
}
__device__ __forceinline__ ull packf2(float lo, float hi) {
    ull r; asm("mov.b64 %0, {%1, %2};" : "=l"(r) : "f"(lo), "f"(hi)); return r;
}
__device__ __forceinline__ float2 unpackf2(ull v) {
    float2 f; asm("mov.b64 {%0, %1}, %2;" : "=f"(f.x), "=f"(f.y) : "l"(v)); return f;
}

// Scratch (sanctioned __device__ globals)
__device__ float g_xs [(size_t)S_DIM * B_DIM * G_DIM];   // [s][b][4D]
__device__ float g_Wc [IN_DIM * G_DIM];
__device__ float g_bc [G_DIM];
__device__ float g_hso[(size_t)B_DIM * S_DIM * D_DIM];   // [b][s][64]
__device__ float g_k  [(size_t)B_DIM * S_DIM * D_DIM];
__device__ float g_v  [(size_t)B_DIM * S_DIM * D_DIM];

// ---------------------------------------------------------------------------
// Kernel 1: fold input projection into sLSTM input weights.
// ---------------------------------------------------------------------------
__global__ void combine_weights(const float* __restrict__ W_in,
                                const float* __restrict__ b_in,
                                const float* __restrict__ W_s,
                                const float* __restrict__ b_s) {
    int j = threadIdx.x;
    int d = blockIdx.x;
    if (d < IN_DIM) {
        float acc = 0.f;
#pragma unroll
        for (int e = 0; e < D_DIM; e++)
            acc += W_in[d * D_DIM + e] * W_s[e * G_DIM + j];
        g_Wc[d * G_DIM + j] = acc;
    } else {
        float acc = b_s[j];
#pragma unroll
        for (int e = 0; e < D_DIM; e++)
            acc += b_in[e] * W_s[e * G_DIM + j];
        g_bc[j] = acc;
    }
}

// ---------------------------------------------------------------------------
// Kernel 2: xs = x @ W_comb + b_comb  (unchanged from 555us baseline)
// ---------------------------------------------------------------------------
__global__ __launch_bounds__(256) void xs_gemm(const float* __restrict__ x) {
    __shared__ __align__(16) float xsm[TILE_R][IN_DIM];
    int t = threadIdx.x;
    int row0 = blockIdx.x * TILE_R;

    const float4* xg = reinterpret_cast<const float4*>(x + (size_t)row0 * IN_DIM);
    float4* xs4 = reinterpret_cast<float4*>(&xsm[0][0]);
#pragma unroll
    for (int i = 0; i < (TILE_R * IN_DIM / 4) / 256; i++)
        xs4[t + i * 256] = xg[t + i * 256];

    ull w2[64];
#pragma unroll
    for (int i = 0; i < 64; i++)
        w2[i] = packf2(g_Wc[(2 * i) * G_DIM + t], g_Wc[(2 * i + 1) * G_DIM + t]);
    float bc = g_bc[t];
    __syncthreads();

    for (int r = 0; r < TILE_R; r += 4) {
        ull a0 = 0, a1 = 0, a2 = 0, a3 = 0;
        const ulonglong2* p0 = reinterpret_cast<const ulonglong2*>(xsm[r + 0]);
        const ulonglong2* p1 = reinterpret_cast<const ulonglong2*>(xsm[r + 1]);
        const ulonglong2* p2 = reinterpret_cast<const ulonglong2*>(xsm[r + 2]);
        const ulonglong2* p3 = reinterpret_cast<const ulonglong2*>(xsm[r + 3]);
#pragma unroll
        for (int dq = 0; dq < 32; dq++) {
            ulonglong2 v0 = p0[dq]; ffma2(a0, v0.x, w2[2*dq]); ffma2(a0, v0.y, w2[2*dq+1]);
            ulonglong2 v1 = p1[dq]; ffma2(a1, v1.x, w2[2*dq]); ffma2(a1, v1.y, w2[2*dq+1]);
            ulonglong2 v2 = p2[dq]; ffma2(a2, v2.x, w2[2*dq]); ffma2(a2, v2.y, w2[2*dq+1]);
            ulonglong2 v3 = p3[dq]; ffma2(a3, v3.x, w2[2*dq]); ffma2(a3, v3.y, w2[2*dq+1]);
        }
#pragma unroll
        for (int rr = 0; rr < 4; rr++) {
            ull av = (rr == 0) ? a0 : (rr == 1) ? a1 : (rr == 2) ? a2 : a3;
            float2 f = unpackf2(av);
            int row = row0 + r + rr;
            int bb = row >> 9;
            int ss = row & 511;
            g_xs[((size_t)ss * B_DIM + bb) * G_DIM + t] = f.x + f.y + bc;
        }
    }
}

// ---------------------------------------------------------------------------
// Kernel 3: minimal sequential core. 1 CTA/batch, 256 threads, 2 barriers/step.
// Only the sLSTM recurrence + LN is sequential; hso is streamed to gmem and
// ALL mLSTM work happens in parallel post-pass kernels.
// ---------------------------------------------------------------------------
__global__ __launch_bounds__(256) void recur2(
    const float* __restrict__ R_s,
    const float* __restrict__ ln_g, const float* __restrict__ ln_b)
{
    __shared__ __align__(16) float hs[64];
    __shared__ __align__(16) float gact[256];

    int t = threadIdx.x;
    int b = blockIdx.x;
    int lane = t & 31;

    ull R2[32];
#pragma unroll
    for (int i = 0; i < 32; i++)
        R2[i] = packf2(R_s[(2 * i) * G_DIM + t], R_s[(2 * i + 1) * G_DIM + t]);

    // warp-0 constants
    float cs0 = 0.f, cs1 = 0.f, ns0 = 1.f, ns1 = 1.f;
    float g0 = 0.f, g1 = 0.f, lb0 = 0.f, lb1 = 0.f;
    const int d0 = lane, d1 = lane + 32;
    if (t < 32) {
        g0 = ln_g[d0]; g1 = ln_g[d1]; lb0 = ln_b[d0]; lb1 = ln_b[d1];
    }
    if (t < 64) hs[t] = 0.f;
    __syncthreads();

    const size_t BG = (size_t)B_DIM * G_DIM;
    const float* xsp = g_xs + (size_t)b * G_DIM + t;
    float gnext = xsp[0];
    float* hso_out = g_hso + (size_t)b * S_DIM * D_DIM;

    for (int s = 0; s < S_DIM; s++) {
        // ---- A: g = xs(s) + hs @ R_s ; activation ----
        float gv = gnext;
        {
            int sn = (s + 1 < S_DIM) ? (s + 1) : s;
            gnext = xsp[(size_t)sn * BG];
        }
        {
            ull a0 = 0, a1 = 0, a2 = 0, a3 = 0;
            const ulonglong2* h2 = reinterpret_cast<const ulonglong2*>(hs);
#pragma unroll
            for (int q = 0; q < 8; q++) {
                ulonglong2 u = h2[2 * q];
                ulonglong2 w = h2[2 * q + 1];
                ffma2(a0, u.x, R2[4 * q]);
                ffma2(a1, u.y, R2[4 * q + 1]);
                ffma2(a2, w.x, R2[4 * q + 2]);
                ffma2(a3, w.y, R2[4 * q + 3]);
            }
            a0 = addf2(a0, a1); a2 = addf2(a2, a3); a0 = addf2(a0, a2);
            float2 p = unpackf2(a0);
            gv += p.x + p.y;
        }
        float act;
        if (t < 64) {                       // tanh
            float e = __expf(2.f * gv);
            act = 1.f - __fdividef(2.f, e + 1.f);
        } else if (t < 128) {               // exp
            act = __expf(gv);
        } else {                            // sigmoid
            float e = __expf(-gv);
            act = __fdividef(1.f, 1.f + e);
        }
        gact[t] = act;
        __syncthreads();                                   // s1

        // ---- B (warp 0): state + LN; stream hso to gmem ----
        if (t < 32) {
            float z0 = gact[d0], i0 = gact[64 + d0], f0 = gact[128 + d0], o0 = gact[192 + d0];
            float z1 = gact[d1], i1 = gact[64 + d1], f1 = gact[128 + d1], o1 = gact[192 + d1];
            cs0 = f0 * cs0 + i0 * z0; ns0 = f0 * ns0 + i0;
            cs1 = f1 * cs1 + i1 * z1; ns1 = f1 * ns1 + i1;
            float h0 = __fdividef(o0 * cs0, ns0);
            float h1 = __fdividef(o1 * cs1, ns1);
            hs[d0] = h0; hs[d1] = h1;
            float r1 = h0 + h1;
            float r2 = h0 * h0 + h1 * h1;
#pragma unroll
            for (int off = 16; off > 0; off >>= 1) {
                r1 += __shfl_xor_sync(0xffffffffu, r1, off);
                r2 += __shfl_xor_sync(0xffffffffu, r2, off);
            }
            float mu = r1 * 0.015625f;
            float inv = rsqrtf(r2 * 0.015625f - mu * mu + 1e-5f);
            hso_out[s * D_DIM + d0] = (h0 - mu) * inv * g0 + lb0;
            hso_out[s * D_DIM + d1] = (h1 - mu) * inv * g1 + lb1;
        }
        __syncthreads();                                   // s2
    }
}

// ---------------------------------------------------------------------------
// Kernel 4: k/v projections over all (b,s) rows in parallel.
// k = (hso @ Wk) / 8 ;  v = hso @ Wv
// ---------------------------------------------------------------------------
__global__ __launch_bounds__(256) void proj(const float* __restrict__ Wk,
                                            const float* __restrict__ Wv) {
    __shared__ __align__(16) float hsm[64][64];
    int t = threadIdx.x;
    int rg = t >> 7;            // row group 0/1 (32 rows each)
    int col = t & 127;          // 0..63 -> k, 64..127 -> v
    size_t row0 = (size_t)blockIdx.x * 64;

    const float4* hg = reinterpret_cast<const float4*>(g_hso + row0 * D_DIM);
    float4* hsm4 = reinterpret_cast<float4*>(&hsm[0][0]);
#pragma unroll
    for (int i = 0; i < 4; i++)
        hsm4[t + i * 256] = hg[t + i * 256];

    const float* Wsel = (col < 64) ? Wk : Wv;
    const int c = col & 63;
    ull W2[32];
#pragma unroll
    for (int i = 0; i < 32; i++)
        W2[i] = packf2(Wsel[(2 * i) * 64 + c], Wsel[(2 * i + 1) * 64 + c]);
    float scale = (col < 64) ? 0.125f : 1.f;
    float* outp = (col < 64) ? g_k : g_v;
    __syncthreads();

    for (int r = 0; r < 32; r += 2) {
        int row = rg * 32 + r;
        ull a0 = 0, a1 = 0, b0 = 0, b1 = 0;
        const ulonglong2* h0 = reinterpret_cast<const ulonglong2*>(hsm[row]);
        const ulonglong2* h1 = reinterpret_cast<const ulonglong2*>(hsm[row + 1]);
#pragma unroll
        for (int q = 0; q < 16; q++) {
            ulonglong2 u = h0[q];
            ffma2(a0, u.x, W2[2 * q]);
            ffma2(a1, u.y, W2[2 * q + 1]);
            ulonglong2 w = h1[q];
            ffma2(b0, w.x, W2[2 * q]);
            ffma2(b1, w.y, W2[2 * q + 1]);
        }
        a0 = addf2(a0, a1); b0 = addf2(b0, b1);
        float2 fa = unpackf2(a0);
        float2 fb = unpackf2(b0);
        outp[(row0 + row) * 64 + c]     = (fa.x + fa.y) * scale;
        outp[(row0 + row + 1) * 64 + c] = (fb.x + fb.y) * scale;
    }
}

// ---------------------------------------------------------------------------
// Kernel 5: per-batch scan + weighted sums + fusion gate.
//   w(s) = im(s) * prod_{s'>s} fm(s')       (same product order as reference)
//   num  = sum_s w(s)(k(s).q) v(s) ; den = |sum_s w(s)(k(s).q)| clamped
// ---------------------------------------------------------------------------
__global__ __launch_bounds__(64) void scan(
    const float* __restrict__ Wq,
    const float* __restrict__ wi, const float* __restrict__ bi_p,
    const float* __restrict__ wf, const float* __restrict__ bf_p,
    const float* __restrict__ Wo, const float* __restrict__ bo,
    const float* __restrict__ W_fuse, const float* __restrict__ b_fuse,
    float* __restrict__ out)
{
    __shared__ float hlast[64], qv[64], omv[64], hm[64];
    __shared__ float wis[64], wfs[64];
    __shared__ float imv[512], fmv[512], cp[512], av[512];

    int t = threadIdx.x;        // 0..63
    int b = blockIdx.x;
    const float* hso_b = g_hso + (size_t)b * S_DIM * D_DIM;

    hlast[t] = hso_b[511 * 64 + t];
    wis[t] = wi[t]; wfs[t] = wf[t];
    __syncthreads();

    // q and om from hso(511)
    {
        float aq = 0.f, ao = bo[t];
#pragma unroll 8
        for (int d = 0; d < 64; d++) {
            float h = hlast[d];
            aq += h * Wq[d * 64 + t];
            ao += h * Wo[d * 64 + t];
        }
        qv[t] = aq;
        omv[t] = __fdividef(1.f, 1.f + __expf(-ao));
    }

    // im/fm for all steps (8 per thread)
    float bi = bi_p[0], bf = bf_p[0];
    for (int s = t; s < S_DIM; s += 64) {
        const float* hr = hso_b + s * 64;
        float pi = bi, pf = bf;
#pragma unroll 8
        for (int d = 0; d < 64; d++) {
            float h = hr[d];
            pi += h * wis[d];
            pf += h * wfs[d];
        }
        imv[s] = __expf(pi);
        fmv[s] = __fdividef(1.f, 1.f + __expf(-pf));
    }
    __syncthreads();

    // suffix product of fm (serial, matches reference multiply order)
    if (t == 0) {
        float c = 1.f;
        cp[511] = 1.f;
        for (int s = 510; s >= 0; s--) { c *= fmv[s + 1]; cp[s] = c; }
    }
    __syncthreads();

    // a(s) = im(s)*cp(s)*(k(s).q)
    const float* kb = g_k + (size_t)b * S_DIM * D_DIM;
    for (int s = t; s < S_DIM; s += 64) {
        const float* kr = kb + s * 64;
        float kq = 0.f;
#pragma unroll 8
        for (int d = 0; d < 64; d++) kq += kr[d] * qv[d];
        av[s] = imv[s] * cp[s] * kq;
    }
    __syncthreads();

    // num_j = sum_s a(s) v_j(s) ; den = sum_s a(s)
    const float* vb = g_v + (size_t)b * S_DIM * D_DIM;
    float num = 0.f, den = 0.f;
#pragma unroll 4
    for (int s = 0; s < S_DIM; s++) {
        float a = av[s];
        num += a * vb[s * 64 + t];
        den += a;
    }
    den = fmaxf(fabsf(den), 1.f);
    hm[t] = omv[t] * num / den;
    __syncthreads();

    // fusion gate
    float gp = b_fuse[t];
#pragma unroll 8
    for (int r = 0; r < 64; r++) gp += hlast[r] * W_fuse[r * 64 + t];
#pragma unroll 8
    for (int r = 0; r < 64; r++) gp += hm[r] * W_fuse[(64 + r) * 64 + t];
    float gate = __fdividef(1.f, 1.f + __expf(-gp));
    out[b * 64 + t] = gate * hm[t] + (1.f - gate) * hlast[t];
}

// ---------------------------------------------------------------------------
extern "C" void kernel_launch(void* const* d_in, const int* in_sizes, int n_in,
                              void* d_out, int out_size) {
    const float* x      = (const float*)d_in[0];
    const float* W_in   = (const float*)d_in[1];
    const float* b_in   = (const float*)d_in[2];
    const float* W_s    = (const float*)d_in[3];
    const float* R_s    = (const float*)d_in[4];
    const float* b_s    = (const float*)d_in[5];
    const float* ln_g   = (const float*)d_in[6];
    const float* ln_b   = (const float*)d_in[7];
    const float* Wq     = (const float*)d_in[8];
    const float* Wk     = (const float*)d_in[9];
    const float* Wv     = (const float*)d_in[10];
    const float* wi     = (const float*)d_in[11];
    const float* bi     = (const float*)d_in[12];
    const float* wf     = (const float*)d_in[13];
    const float* bf     = (const float*)d_in[14];
    const float* Wo     = (const float*)d_in[15];
    const float* bo     = (const float*)d_in[16];
    const float* W_fuse = (const float*)d_in[17];
    const float* b_fuse = (const float*)d_in[18];
    float* out = (float*)d_out;

    combine_weights<<<IN_DIM + 1, G_DIM>>>(W_in, b_in, W_s, b_s);
    xs_gemm<<<(B_DIM * S_DIM) / TILE_R, 256>>>(x);
    recur2<<<B_DIM, 256>>>(R_s, ln_g, ln_b);
    proj<<<(B_DIM * S_DIM) / 64, 256>>>(Wk, Wv);
    scan<<<B_DIM, 64>>>(Wq, wi, bi, wf, bf, Wo, bo, W_fuse, b_fuse, out);
}